// round 12
// baseline (speedup 1.0000x reference)
#include <cuda_runtime.h>
#include <cuda_bf16.h>
#include <cstdint>
#include <math.h>

#define N_  4
#define C_  512
#define CT_ 512
#define L_  256
#define S_  4096
#define H_  16
#define D_  32

// bf16-split K/V in fragment-ready layouts (written by proj kernel)
// K: [n][h][l(256)][kp(16)]   kp = channel-pair within head
// V: [n][h][d(32)][lp(128)]   lp = l-pair
__device__ uint32_t g_KH[(size_t)N_ * H_ * L_ * 16];
__device__ uint32_t g_KL[(size_t)N_ * H_ * L_ * 16];
__device__ uint32_t g_VH[(size_t)N_ * H_ * D_ * 128];
__device__ uint32_t g_VL[(size_t)N_ * H_ * D_ * 128];

// ---------------- helpers ----------------
__device__ __forceinline__ float ex2f(float x) {
    float r; asm("ex2.approx.f32 %0, %1;" : "=f"(r) : "f"(x)); return r;
}
__device__ __forceinline__ uint32_t pack_bf2(float lo, float hi) {
    uint32_t r; asm("cvt.rn.bf16x2.f32 %0, %1, %2;" : "=r"(r) : "f"(hi), "f"(lo)); return r;
}
__device__ __forceinline__ float bf_lo(uint32_t r) { return __uint_as_float(r << 16); }
__device__ __forceinline__ float bf_hi(uint32_t r) { return __uint_as_float(r & 0xFFFF0000u); }
__device__ __forceinline__ void split2(float x0, float x1, uint32_t& hp, uint32_t& lp) {
    hp = pack_bf2(x0, x1);
    lp = pack_bf2(x0 - bf_lo(hp), x1 - bf_hi(hp));
}
__device__ __forceinline__ void mma16816(float* c, const uint32_t* a, uint32_t b0, uint32_t b1) {
    asm volatile("mma.sync.aligned.m16n8k16.row.col.f32.bf16.bf16.f32 "
                 "{%0,%1,%2,%3}, {%4,%5,%6,%7}, {%8,%9}, {%0,%1,%2,%3};"
                 : "+f"(c[0]), "+f"(c[1]), "+f"(c[2]), "+f"(c[3])
                 : "r"(a[0]), "r"(a[1]), "r"(a[2]), "r"(a[3]), "r"(b0), "r"(b1));
}
__device__ __forceinline__ void ldmx4(uint32_t* r, uint32_t addr) {
    asm volatile("ldmatrix.sync.aligned.m8n8.x4.shared.b16 {%0,%1,%2,%3}, [%4];"
                 : "=r"(r[0]), "=r"(r[1]), "=r"(r[2]), "=r"(r[3]) : "r"(addr));
}
__device__ __forceinline__ uint32_t smem_u32(const void* p) {
    uint32_t a;
    asm("{ .reg .u64 t; cvta.to.shared.u64 t, %1; cvt.u32.u64 %0, t; }" : "=r"(a) : "l"(p));
    return a;
}

// ---------------------------------------------------------------------------
// Kernel A: K/V projection as bf16-split mma GEMM (3-pass), epilogue emits
// bf16 hi/lo split in fragment-ready global layouts.
// Block tile: M=128 (out channels), N=128 (l), K=512 (ct), chunks of 32.
// grid = (2, 4, 8) -> 64 blocks, 256 threads.
// ---------------------------------------------------------------------------
#define PJ_ASH  0
#define PJ_ASL  8704
#define PJ_BSH  17408
#define PJ_BSL  27648
#define PJ_TOT  67584          // Csm[128][132] f32 reuses from offset 0

extern "C" __global__ void __launch_bounds__(256, 1)
proj_mma_kernel(const float* __restrict__ token,
                const float* __restrict__ Wv, const float* __restrict__ bv,
                const float* __restrict__ Wk, const float* __restrict__ bk)
{
    extern __shared__ char smem[];
    uint32_t* ASH = (uint32_t*)(smem + PJ_ASH);
    uint32_t* ASL = (uint32_t*)(smem + PJ_ASL);
    uint32_t* BSH = (uint32_t*)(smem + PJ_BSH);
    uint32_t* BSL = (uint32_t*)(smem + PJ_BSL);
    float*    Csm = (float*)smem;
    const uint32_t sb = smem_u32(smem);

    const int t    = threadIdx.x;
    const int lane = t & 31;
    const int wid  = t >> 5;
    const int g    = lane >> 2;
    const int tig  = lane & 3;
    const int l0 = blockIdx.x * 128;
    const int o0 = blockIdx.y * 128;
    const int n = blockIdx.z >> 1, which = blockIdx.z & 1;   // 0 -> V, 1 -> K
    const float* __restrict__ W    = which ? Wk : Wv;
    const float* __restrict__ bias = which ? bk : bv;
    const float* tb = token + (size_t)n * CT_ * L_;

    const uint32_t kbase = sb + (lane < 16 ? PJ_BSH : PJ_BSL)
                         + ((uint32_t)(lane & 7) * 20 + ((uint32_t)((lane >> 3) & 1)) * 4) * 4;
    const int r0 = wid * 16;

    float c[16][4] = {};

    for (int kc = 0; kc < CT_; kc += 32) {
        __syncthreads();
        // stage A: W[o0+row][kc + 2cp..2cp+1] -> ASH/ASL[cp][row]
        #pragma unroll
        for (int i = t; i < 2048; i += 256) {
            int row = i >> 4, cp = i & 15;
            float2 w = *(const float2*)(W + (size_t)(o0 + row) * CT_ + kc + 2 * cp);
            uint32_t hp, lp; split2(w.x, w.y, hp, lp);
            ASH[cp * 136 + row] = hp;
            ASL[cp * 136 + row] = lp;
        }
        // stage B: token[kc+2cp..][l0+l] -> BSH/BSL[l][cp]
        #pragma unroll
        for (int i = t; i < 2048; i += 256) {
            int cp = i >> 7, l = i & 127;
            float t0 = tb[(size_t)(kc + 2 * cp) * L_ + l0 + l];
            float t1 = tb[(size_t)(kc + 2 * cp + 1) * L_ + l0 + l];
            uint32_t hp, lp; split2(t0, t1, hp, lp);
            BSH[l * 20 + cp] = hp;
            BSL[l * 20 + cp] = lp;
        }
        __syncthreads();

        uint32_t aH[2][4], aL[2][4];
        #pragma unroll
        for (int ks = 0; ks < 2; ks++) {
            int p0 = ks * 8 + tig;
            aH[ks][0] = ASH[p0 * 136 + r0 + g];
            aH[ks][1] = ASH[p0 * 136 + r0 + g + 8];
            aH[ks][2] = ASH[(p0 + 4) * 136 + r0 + g];
            aH[ks][3] = ASH[(p0 + 4) * 136 + r0 + g + 8];
            aL[ks][0] = ASL[p0 * 136 + r0 + g];
            aL[ks][1] = ASL[p0 * 136 + r0 + g + 8];
            aL[ks][2] = ASL[(p0 + 4) * 136 + r0 + g];
            aL[ks][3] = ASL[(p0 + 4) * 136 + r0 + g + 8];
        }
        #pragma unroll
        for (int nt = 0; nt < 16; nt++) {
            const uint32_t ka = kbase + (uint32_t)nt * 640;
            #pragma unroll
            for (int ks = 0; ks < 2; ks++) {
                uint32_t b[4];
                ldmx4(b, ka + ks * 32);
                mma16816(c[nt], aH[ks], b[0], b[1]);   // hi*hi
                mma16816(c[nt], aH[ks], b[2], b[3]);   // hi*lo
                mma16816(c[nt], aL[ks], b[0], b[1]);   // lo*hi
            }
        }
    }
    __syncthreads();

    // dump C to smem [row=channel 128][col=l 132-stride]
    #pragma unroll
    for (int nt = 0; nt < 16; nt++) {
        int col = nt * 8 + 2 * tig;
        Csm[(r0 + g) * 132 + col]           = c[nt][0];
        Csm[(r0 + g) * 132 + col + 1]       = c[nt][1];
        Csm[(r0 + g + 8) * 132 + col]       = c[nt][2];
        Csm[(r0 + g + 8) * 132 + col + 1]   = c[nt][3];
    }
    __syncthreads();

    if (which) {
        // K: pack channel-pairs -> g_KH/g_KL[((n*16+h)*256 + l)*16 + kp]
        #pragma unroll
        for (int i = t; i < 8192; i += 256) {
            int op = i >> 7, l = i & 127;
            int ch = o0 + 2 * op;
            float v0 = Csm[(2 * op) * 132 + l]     + bias[ch];
            float v1 = Csm[(2 * op + 1) * 132 + l] + bias[ch + 1];
            uint32_t hp, lp; split2(v0, v1, hp, lp);
            int h = ch >> 5, kp = (ch & 31) >> 1;
            size_t dst = ((size_t)(n * H_ + h) * L_ + l0 + l) * 16 + kp;
            g_KH[dst] = hp;
            g_KL[dst] = lp;
        }
    } else {
        // V: pack l-pairs -> g_VH/g_VL[((n*16+h)*32 + d)*128 + lp]
        #pragma unroll
        for (int i = t; i < 8192; i += 256) {
            int r = i >> 6, lc = i & 63;
            int ch = o0 + r;
            float bb = bias[ch];
            float v0 = Csm[r * 132 + 2 * lc]     + bb;
            float v1 = Csm[r * 132 + 2 * lc + 1] + bb;
            uint32_t hp, lp; split2(v0, v1, hp, lp);
            int h = ch >> 5, d = ch & 31;
            size_t dst = ((size_t)(n * H_ + h) * D_ + d) * 128 + (l0 >> 1) + lc;
            g_VH[dst] = hp;
            g_VL[dst] = lp;
        }
    }
}

// ---------------------------------------------------------------------------
// Kernel B: mma.sync attention — round-8/11 mainloop, staging = pure copies.
// ---------------------------------------------------------------------------
#define SB_F    0          // 32x132 f32 (F; Osm after mainloop)
#define SB_WQ   16896      // 1024 f32
#define SB_QHI  20992      // 16x136 u32
#define SB_KHI  29696      // 256x20 u32
#define SB_KLO  50176
#define SB_VHI  70656      // 32x132 u32
#define SB_VLO  87552
#define SB_TOT  104448

extern "C" __global__ void __launch_bounds__(256, 2)
attn_mma_kernel(const float* __restrict__ feature,
                const float* __restrict__ Wq, const float* __restrict__ bq,
                float* __restrict__ dout)
{
    extern __shared__ char smem[];
    float*    smf = (float*)smem;
    uint32_t* QH  = (uint32_t*)(smem + SB_QHI);
    uint32_t* KH  = (uint32_t*)(smem + SB_KHI);
    uint32_t* KL  = (uint32_t*)(smem + SB_KLO);
    uint32_t* VH  = (uint32_t*)(smem + SB_VHI);
    uint32_t* VL  = (uint32_t*)(smem + SB_VLO);
    float*    Osm = (float*)smem;

    const int t    = threadIdx.x;
    const int lane = t & 31;
    const int wid  = t >> 5;
    const int g    = lane >> 2;
    const int tig  = lane & 3;
    const int s0 = blockIdx.x * 128;
    const int h  = blockIdx.y;
    const int n  = blockIdx.z;
    const uint32_t sb = smem_u32(smem);

    // ---------------- stage tiles (pure copies) ----------------
    const float* fb = feature + ((size_t)(n * C_ + h * D_)) * S_ + s0;
    #pragma unroll
    for (int i = t; i < 1024; i += 256) {
        int row = i >> 5, c4 = (i & 31) << 2;
        *(float4*)&smf[row * 132 + c4] = *(const float4*)(fb + (size_t)row * S_ + c4);
    }
    #pragma unroll
    for (int i = t; i < 1024; i += 256)
        smf[SB_WQ/4 + i] = Wq[h * 1024 + i];

    const uint32_t* gkh = g_KH + (size_t)(n * H_ + h) * L_ * 16;
    const uint32_t* gkl = g_KL + (size_t)(n * H_ + h) * L_ * 16;
    #pragma unroll
    for (int i = t; i < 1024; i += 256) {                 // K: 256 rows x 16 u32
        int l = i >> 2, c = (i & 3) << 2;
        *(uint4*)&KH[l * 20 + c] = *(const uint4*)(gkh + l * 16 + c);
        *(uint4*)&KL[l * 20 + c] = *(const uint4*)(gkl + l * 16 + c);
    }
    const uint32_t* gvh = g_VH + (size_t)(n * H_ + h) * D_ * 128;
    const uint32_t* gvl = g_VL + (size_t)(n * H_ + h) * D_ * 128;
    #pragma unroll
    for (int i = t; i < 1024; i += 256) {                 // V: 32 rows x 128 u32
        int d = i >> 5, c = (i & 31) << 2;
        *(uint4*)&VH[d * 132 + c] = *(const uint4*)(gvh + d * 128 + c);
        *(uint4*)&VL[d * 132 + c] = *(const uint4*)(gvl + d * 128 + c);
    }
    __syncthreads();

    // ---------------- Q projection -> bf16 (hi only) in smem ----------------
    {
        const int row = t & 127;
        const int d0  = (t >> 7) << 4;
        float acc[16] = {};
        #pragma unroll 8
        for (int i = 0; i < 32; i++) {
            float f = smf[i * 132 + row];
            #pragma unroll
            for (int dd = 0; dd < 16; dd++)
                acc[dd] += smf[SB_WQ/4 + (d0 + dd) * 32 + i] * f;
        }
        const float scale = 0.2550354839f;                // (1/sqrt(32))*log2(e)
        #pragma unroll
        for (int j = 0; j < 8; j++) {
            int d = d0 + 2 * j;
            float q0 = (acc[2*j]   + bq[h*D_ + d])   * scale;
            float q1 = (acc[2*j+1] + bq[h*D_ + d+1]) * scale;
            QH[(d >> 1) * 136 + row] = pack_bf2(q0, q1);
        }
    }
    __syncthreads();

    const int r0 = wid * 16;
    uint32_t aH[2][4];
    #pragma unroll
    for (int ks = 0; ks < 2; ks++) {
        int p0 = ks * 8 + tig;
        aH[ks][0] = QH[p0 * 136 + r0 + g];
        aH[ks][1] = QH[p0 * 136 + r0 + g + 8];
        aH[ks][2] = QH[(p0 + 4) * 136 + r0 + g];
        aH[ks][3] = QH[(p0 + 4) * 136 + r0 + g + 8];
    }
    __syncthreads();

    const uint32_t kbase = sb + (lane < 16 ? SB_KHI : SB_KLO)
                         + ((uint32_t)(lane & 7) * 20 + ((uint32_t)((lane >> 3) & 1)) * 4) * 4;
    const uint32_t vbase = sb + (lane < 16 ? SB_VHI : SB_VLO)
                         + ((uint32_t)(lane & 7) * 132 + ((uint32_t)((lane >> 3) & 1)) * 4) * 4;

    float o[4][4] = {};
    float sum0 = 0.f, sum1 = 0.f;

    #pragma unroll 1
    for (int cb = 0; cb < 8; cb++) {
        float c[4][4] = {};
        #pragma unroll
        for (int nt = 0; nt < 4; nt++) {
            const uint32_t ka = kbase + (uint32_t)(cb * 32 + nt * 8) * 80;
            #pragma unroll
            for (int ks = 0; ks < 2; ks++) {
                uint32_t b[4];
                ldmx4(b, ka + ks * 32);
                mma16816(c[nt], aH[ks], b[0], b[1]);
                mma16816(c[nt], aH[ks], b[2], b[3]);
            }
        }
        float e[4][4];
        #pragma unroll
        for (int nt = 0; nt < 4; nt++) {
            e[nt][0] = ex2f(c[nt][0]);
            e[nt][1] = ex2f(c[nt][1]);
            e[nt][2] = ex2f(c[nt][2]);
            e[nt][3] = ex2f(c[nt][3]);
            sum0 += e[nt][0] + e[nt][1];
            sum1 += e[nt][2] + e[nt][3];
        }
        uint32_t pH[2][4];
        #pragma unroll
        for (int kc = 0; kc < 2; kc++) {
            int t0 = 2 * kc, t1 = 2 * kc + 1;
            pH[kc][0] = pack_bf2(e[t0][0], e[t0][1]);
            pH[kc][1] = pack_bf2(e[t0][2], e[t0][3]);
            pH[kc][2] = pack_bf2(e[t1][0], e[t1][1]);
            pH[kc][3] = pack_bf2(e[t1][2], e[t1][3]);
        }
        #pragma unroll
        for (int dt = 0; dt < 4; dt++) {
            const uint32_t va = vbase + (uint32_t)dt * 4224 + (uint32_t)cb * 64;
            #pragma unroll
            for (int kc = 0; kc < 2; kc++) {
                uint32_t v[4];
                ldmx4(v, va + kc * 32);
                mma16816(o[dt], pH[kc], v[0], v[1]);
                mma16816(o[dt], pH[kc], v[2], v[3]);
            }
        }
    }

    sum0 += __shfl_xor_sync(0xffffffffu, sum0, 1);
    sum0 += __shfl_xor_sync(0xffffffffu, sum0, 2);
    sum1 += __shfl_xor_sync(0xffffffffu, sum1, 1);
    sum1 += __shfl_xor_sync(0xffffffffu, sum1, 2);
    float rinv0 = __fdividef(1.0f, sum0);
    float rinv1 = __fdividef(1.0f, sum1);

    __syncthreads();
    #pragma unroll
    for (int dt = 0; dt < 4; dt++) {
        int d = dt * 8 + 2 * tig;
        Osm[d * 132 + r0 + g]           = o[dt][0] * rinv0;
        Osm[(d + 1) * 132 + r0 + g]     = o[dt][1] * rinv0;
        Osm[d * 132 + r0 + g + 8]       = o[dt][2] * rinv1;
        Osm[(d + 1) * 132 + r0 + g + 8] = o[dt][3] * rinv1;
    }
    __syncthreads();

    float* ob = dout + ((size_t)(n * C_ + h * D_)) * S_ + s0;
    #pragma unroll
    for (int j = 0; j < 4; j++) {
        int i = t + j * 256;
        int d = i >> 5, c4 = (i & 31) << 2;
        float4 ov = *(float4*)&Osm[d * 132 + c4];
        float4 fv = *(const float4*)(fb + (size_t)d * S_ + c4);
        ov.x += fv.x; ov.y += fv.y; ov.z += fv.z; ov.w += fv.w;
        *(float4*)(ob + (size_t)d * S_ + c4) = ov;
    }
}

// ---------------------------------------------------------------------------
extern "C" void kernel_launch(void* const* d_in, const int* in_sizes, int n_in,
                              void* d_out, int out_size)
{
    const float* feature = (const float*)d_in[0];
    const float* token   = (const float*)d_in[1];
    const float* Wv      = (const float*)d_in[2];
    const float* bv      = (const float*)d_in[3];
    const float* Wk      = (const float*)d_in[4];
    const float* bk      = (const float*)d_in[5];
    const float* Wq      = (const float*)d_in[6];
    const float* bq      = (const float*)d_in[7];
    float* out = (float*)d_out;

    cudaFuncSetAttribute(proj_mma_kernel,
                         cudaFuncAttributeMaxDynamicSharedMemorySize, PJ_TOT);
    cudaFuncSetAttribute(attn_mma_kernel,
                         cudaFuncAttributeMaxDynamicSharedMemorySize, SB_TOT);

    proj_mma_kernel<<<dim3(L_/128, C_/128, N_*2), 256, PJ_TOT>>>(token, Wv, bv, Wk, bk);
    attn_mma_kernel<<<dim3(S_/128, H_, N_), 256, SB_TOT>>>(feature, Wq, bq, out);
}

// round 13
// speedup vs baseline: 1.0731x; 1.0731x over previous
#include <cuda_runtime.h>
#include <cuda_bf16.h>
#include <cstdint>
#include <math.h>

#define N_  4
#define C_  512
#define CT_ 512
#define L_  256
#define S_  4096
#define H_  16
#define D_  32

// bf16-split K/V in fragment-ready layouts (written by proj kernel)
// K: [n][h][l(256)][kp(16)]   kp = channel-pair within head
// V: [n][h][d(32)][lp(128)]   lp = l-pair
__device__ uint32_t g_KH[(size_t)N_ * H_ * L_ * 16];
__device__ uint32_t g_KL[(size_t)N_ * H_ * L_ * 16];
__device__ uint32_t g_VH[(size_t)N_ * H_ * D_ * 128];
__device__ uint32_t g_VL[(size_t)N_ * H_ * D_ * 128];

// ---------------- helpers ----------------
__device__ __forceinline__ float ex2f(float x) {
    float r; asm("ex2.approx.f32 %0, %1;" : "=f"(r) : "f"(x)); return r;
}
__device__ __forceinline__ uint32_t pack_bf2(float lo, float hi) {
    uint32_t r; asm("cvt.rn.bf16x2.f32 %0, %1, %2;" : "=r"(r) : "f"(hi), "f"(lo)); return r;
}
__device__ __forceinline__ float bf_lo(uint32_t r) { return __uint_as_float(r << 16); }
__device__ __forceinline__ float bf_hi(uint32_t r) { return __uint_as_float(r & 0xFFFF0000u); }
__device__ __forceinline__ void split2(float x0, float x1, uint32_t& hp, uint32_t& lp) {
    hp = pack_bf2(x0, x1);
    lp = pack_bf2(x0 - bf_lo(hp), x1 - bf_hi(hp));
}
__device__ __forceinline__ void mma16816(float* c, const uint32_t* a, uint32_t b0, uint32_t b1) {
    asm volatile("mma.sync.aligned.m16n8k16.row.col.f32.bf16.bf16.f32 "
                 "{%0,%1,%2,%3}, {%4,%5,%6,%7}, {%8,%9}, {%0,%1,%2,%3};"
                 : "+f"(c[0]), "+f"(c[1]), "+f"(c[2]), "+f"(c[3])
                 : "r"(a[0]), "r"(a[1]), "r"(a[2]), "r"(a[3]), "r"(b0), "r"(b1));
}
__device__ __forceinline__ void ldmx4(uint32_t* r, uint32_t addr) {
    asm volatile("ldmatrix.sync.aligned.m8n8.x4.shared.b16 {%0,%1,%2,%3}, [%4];"
                 : "=r"(r[0]), "=r"(r[1]), "=r"(r[2]), "=r"(r[3]) : "r"(addr));
}
__device__ __forceinline__ uint32_t smem_u32(const void* p) {
    uint32_t a;
    asm("{ .reg .u64 t; cvta.to.shared.u64 t, %1; cvt.u32.u64 %0, t; }" : "=r"(a) : "l"(p));
    return a;
}

// ---------------------------------------------------------------------------
// Kernel A: K/V projection as bf16-split mma GEMM (3-pass), epilogue emits
// bf16 hi/lo split in fragment-ready global layouts (coalesced stores).
// ---------------------------------------------------------------------------
#define PJ_ASH  0
#define PJ_ASL  8704
#define PJ_BSH  17408
#define PJ_BSL  27648
#define PJ_TOT  67584          // Csm[128][132] f32 reuses from offset 0

extern "C" __global__ void __launch_bounds__(256, 1)
proj_mma_kernel(const float* __restrict__ token,
                const float* __restrict__ Wv, const float* __restrict__ bv,
                const float* __restrict__ Wk, const float* __restrict__ bk)
{
    extern __shared__ char smem[];
    uint32_t* ASH = (uint32_t*)(smem + PJ_ASH);
    uint32_t* ASL = (uint32_t*)(smem + PJ_ASL);
    uint32_t* BSH = (uint32_t*)(smem + PJ_BSH);
    uint32_t* BSL = (uint32_t*)(smem + PJ_BSL);
    float*    Csm = (float*)smem;
    const uint32_t sb = smem_u32(smem);

    const int t    = threadIdx.x;
    const int lane = t & 31;
    const int wid  = t >> 5;
    const int g    = lane >> 2;
    const int tig  = lane & 3;
    const int l0 = blockIdx.x * 128;
    const int o0 = blockIdx.y * 128;
    const int n = blockIdx.z >> 1, which = blockIdx.z & 1;   // 0 -> V, 1 -> K
    const float* __restrict__ W    = which ? Wk : Wv;
    const float* __restrict__ bias = which ? bk : bv;
    const float* tb = token + (size_t)n * CT_ * L_;

    const uint32_t kbase = sb + (lane < 16 ? PJ_BSH : PJ_BSL)
                         + ((uint32_t)(lane & 7) * 20 + ((uint32_t)((lane >> 3) & 1)) * 4) * 4;
    const int r0 = wid * 16;

    float c[16][4] = {};

    for (int kc = 0; kc < CT_; kc += 32) {
        __syncthreads();
        // stage A: W[o0+row][kc + 2cp..2cp+1] -> ASH/ASL[cp][row]
        #pragma unroll
        for (int i = t; i < 2048; i += 256) {
            int row = i >> 4, cp = i & 15;
            float2 w = *(const float2*)(W + (size_t)(o0 + row) * CT_ + kc + 2 * cp);
            uint32_t hp, lp; split2(w.x, w.y, hp, lp);
            ASH[cp * 136 + row] = hp;
            ASL[cp * 136 + row] = lp;
        }
        // stage B: token[kc+2cp..][l0+l] -> BSH/BSL[l][cp]
        #pragma unroll
        for (int i = t; i < 2048; i += 256) {
            int cp = i >> 7, l = i & 127;
            float t0 = tb[(size_t)(kc + 2 * cp) * L_ + l0 + l];
            float t1 = tb[(size_t)(kc + 2 * cp + 1) * L_ + l0 + l];
            uint32_t hp, lp; split2(t0, t1, hp, lp);
            BSH[l * 20 + cp] = hp;
            BSL[l * 20 + cp] = lp;
        }
        __syncthreads();

        uint32_t aH[2][4], aL[2][4];
        #pragma unroll
        for (int ks = 0; ks < 2; ks++) {
            int p0 = ks * 8 + tig;
            aH[ks][0] = ASH[p0 * 136 + r0 + g];
            aH[ks][1] = ASH[p0 * 136 + r0 + g + 8];
            aH[ks][2] = ASH[(p0 + 4) * 136 + r0 + g];
            aH[ks][3] = ASH[(p0 + 4) * 136 + r0 + g + 8];
            aL[ks][0] = ASL[p0 * 136 + r0 + g];
            aL[ks][1] = ASL[p0 * 136 + r0 + g + 8];
            aL[ks][2] = ASL[(p0 + 4) * 136 + r0 + g];
            aL[ks][3] = ASL[(p0 + 4) * 136 + r0 + g + 8];
        }
        #pragma unroll
        for (int nt = 0; nt < 16; nt++) {
            const uint32_t ka = kbase + (uint32_t)nt * 640;
            #pragma unroll
            for (int ks = 0; ks < 2; ks++) {
                uint32_t b[4];
                ldmx4(b, ka + ks * 32);
                mma16816(c[nt], aH[ks], b[0], b[1]);   // hi*hi
                mma16816(c[nt], aH[ks], b[2], b[3]);   // hi*lo
                mma16816(c[nt], aL[ks], b[0], b[1]);   // lo*hi
            }
        }
    }
    __syncthreads();

    // dump C to smem [row=channel 128][col=l 132-stride]
    #pragma unroll
    for (int nt = 0; nt < 16; nt++) {
        int col = nt * 8 + 2 * tig;
        Csm[(r0 + g) * 132 + col]           = c[nt][0];
        Csm[(r0 + g) * 132 + col + 1]       = c[nt][1];
        Csm[(r0 + g + 8) * 132 + col]       = c[nt][2];
        Csm[(r0 + g + 8) * 132 + col + 1]   = c[nt][3];
    }
    __syncthreads();

    if (which) {
        // K epilogue, coalesced: lanes sweep kp fastest -> contiguous stores
        #pragma unroll
        for (int i = t; i < 8192; i += 256) {
            int kp = i & 15;
            int l  = (i >> 4) & 127;
            int hh = i >> 11;                     // head within block 0..3
            int op = hh * 16 + kp;                // channel-pair row in Csm
            int ch = o0 + 2 * op;
            float v0 = Csm[(2 * op) * 132 + l]     + bias[ch];
            float v1 = Csm[(2 * op + 1) * 132 + l] + bias[ch + 1];
            uint32_t hp, lp; split2(v0, v1, hp, lp);
            int h = ch >> 5;
            size_t dst = ((size_t)(n * H_ + h) * L_ + l0 + l) * 16 + kp;
            g_KH[dst] = hp;
            g_KL[dst] = lp;
        }
    } else {
        // V epilogue (already coalesced: consecutive lc -> contiguous)
        #pragma unroll
        for (int i = t; i < 8192; i += 256) {
            int r = i >> 6, lc = i & 63;
            int ch = o0 + r;
            float bb = bias[ch];
            float v0 = Csm[r * 132 + 2 * lc]     + bb;
            float v1 = Csm[r * 132 + 2 * lc + 1] + bb;
            uint32_t hp, lp; split2(v0, v1, hp, lp);
            int h = ch >> 5, d = ch & 31;
            size_t dst = ((size_t)(n * H_ + h) * D_ + d) * 128 + (l0 >> 1) + lc;
            g_VH[dst] = hp;
            g_VL[dst] = lp;
        }
    }
}

// ---------------------------------------------------------------------------
// Kernel B: mma.sync attention — byte-identical to round 12 (90.7us measured)
// ---------------------------------------------------------------------------
#define SB_F    0          // 32x132 f32 (F; Osm after mainloop)
#define SB_WQ   16896      // 1024 f32
#define SB_QHI  20992      // 16x136 u32
#define SB_KHI  29696      // 256x20 u32
#define SB_KLO  50176
#define SB_VHI  70656      // 32x132 u32
#define SB_VLO  87552
#define SB_TOT  104448

extern "C" __global__ void __launch_bounds__(256, 2)
attn_mma_kernel(const float* __restrict__ feature,
                const float* __restrict__ Wq, const float* __restrict__ bq,
                float* __restrict__ dout)
{
    extern __shared__ char smem[];
    float*    smf = (float*)smem;
    uint32_t* QH  = (uint32_t*)(smem + SB_QHI);
    uint32_t* KH  = (uint32_t*)(smem + SB_KHI);
    uint32_t* KL  = (uint32_t*)(smem + SB_KLO);
    uint32_t* VH  = (uint32_t*)(smem + SB_VHI);
    uint32_t* VL  = (uint32_t*)(smem + SB_VLO);
    float*    Osm = (float*)smem;

    const int t    = threadIdx.x;
    const int lane = t & 31;
    const int wid  = t >> 5;
    const int g    = lane >> 2;
    const int tig  = lane & 3;
    const int s0 = blockIdx.x * 128;
    const int h  = blockIdx.y;
    const int n  = blockIdx.z;
    const uint32_t sb = smem_u32(smem);

    // ---------------- stage tiles (pure copies) ----------------
    const float* fb = feature + ((size_t)(n * C_ + h * D_)) * S_ + s0;
    #pragma unroll
    for (int i = t; i < 1024; i += 256) {
        int row = i >> 5, c4 = (i & 31) << 2;
        *(float4*)&smf[row * 132 + c4] = *(const float4*)(fb + (size_t)row * S_ + c4);
    }
    #pragma unroll
    for (int i = t; i < 1024; i += 256)
        smf[SB_WQ/4 + i] = Wq[h * 1024 + i];

    const uint32_t* gkh = g_KH + (size_t)(n * H_ + h) * L_ * 16;
    const uint32_t* gkl = g_KL + (size_t)(n * H_ + h) * L_ * 16;
    #pragma unroll
    for (int i = t; i < 1024; i += 256) {                 // K: 256 rows x 16 u32
        int l = i >> 2, c = (i & 3) << 2;
        *(uint4*)&KH[l * 20 + c] = *(const uint4*)(gkh + l * 16 + c);
        *(uint4*)&KL[l * 20 + c] = *(const uint4*)(gkl + l * 16 + c);
    }
    const uint32_t* gvh = g_VH + (size_t)(n * H_ + h) * D_ * 128;
    const uint32_t* gvl = g_VL + (size_t)(n * H_ + h) * D_ * 128;
    #pragma unroll
    for (int i = t; i < 1024; i += 256) {                 // V: 32 rows x 128 u32
        int d = i >> 5, c = (i & 31) << 2;
        *(uint4*)&VH[d * 132 + c] = *(const uint4*)(gvh + d * 128 + c);
        *(uint4*)&VL[d * 132 + c] = *(const uint4*)(gvl + d * 128 + c);
    }
    __syncthreads();

    // ---------------- Q projection -> bf16 (hi only) in smem ----------------
    {
        const int row = t & 127;
        const int d0  = (t >> 7) << 4;
        float acc[16] = {};
        #pragma unroll 8
        for (int i = 0; i < 32; i++) {
            float f = smf[i * 132 + row];
            #pragma unroll
            for (int dd = 0; dd < 16; dd++)
                acc[dd] += smf[SB_WQ/4 + (d0 + dd) * 32 + i] * f;
        }
        const float scale = 0.2550354839f;                // (1/sqrt(32))*log2(e)
        #pragma unroll
        for (int j = 0; j < 8; j++) {
            int d = d0 + 2 * j;
            float q0 = (acc[2*j]   + bq[h*D_ + d])   * scale;
            float q1 = (acc[2*j+1] + bq[h*D_ + d+1]) * scale;
            QH[(d >> 1) * 136 + row] = pack_bf2(q0, q1);
        }
    }
    __syncthreads();

    const int r0 = wid * 16;
    uint32_t aH[2][4];
    #pragma unroll
    for (int ks = 0; ks < 2; ks++) {
        int p0 = ks * 8 + tig;
        aH[ks][0] = QH[p0 * 136 + r0 + g];
        aH[ks][1] = QH[p0 * 136 + r0 + g + 8];
        aH[ks][2] = QH[(p0 + 4) * 136 + r0 + g];
        aH[ks][3] = QH[(p0 + 4) * 136 + r0 + g + 8];
    }
    __syncthreads();

    const uint32_t kbase = sb + (lane < 16 ? SB_KHI : SB_KLO)
                         + ((uint32_t)(lane & 7) * 20 + ((uint32_t)((lane >> 3) & 1)) * 4) * 4;
    const uint32_t vbase = sb + (lane < 16 ? SB_VHI : SB_VLO)
                         + ((uint32_t)(lane & 7) * 132 + ((uint32_t)((lane >> 3) & 1)) * 4) * 4;

    float o[4][4] = {};
    float sum0 = 0.f, sum1 = 0.f;

    #pragma unroll 1
    for (int cb = 0; cb < 8; cb++) {
        float c[4][4] = {};
        #pragma unroll
        for (int nt = 0; nt < 4; nt++) {
            const uint32_t ka = kbase + (uint32_t)(cb * 32 + nt * 8) * 80;
            #pragma unroll
            for (int ks = 0; ks < 2; ks++) {
                uint32_t b[4];
                ldmx4(b, ka + ks * 32);
                mma16816(c[nt], aH[ks], b[0], b[1]);
                mma16816(c[nt], aH[ks], b[2], b[3]);
            }
        }
        float e[4][4];
        #pragma unroll
        for (int nt = 0; nt < 4; nt++) {
            e[nt][0] = ex2f(c[nt][0]);
            e[nt][1] = ex2f(c[nt][1]);
            e[nt][2] = ex2f(c[nt][2]);
            e[nt][3] = ex2f(c[nt][3]);
            sum0 += e[nt][0] + e[nt][1];
            sum1 += e[nt][2] + e[nt][3];
        }
        uint32_t pH[2][4];
        #pragma unroll
        for (int kc = 0; kc < 2; kc++) {
            int t0 = 2 * kc, t1 = 2 * kc + 1;
            pH[kc][0] = pack_bf2(e[t0][0], e[t0][1]);
            pH[kc][1] = pack_bf2(e[t0][2], e[t0][3]);
            pH[kc][2] = pack_bf2(e[t1][0], e[t1][1]);
            pH[kc][3] = pack_bf2(e[t1][2], e[t1][3]);
        }
        #pragma unroll
        for (int dt = 0; dt < 4; dt++) {
            const uint32_t va = vbase + (uint32_t)dt * 4224 + (uint32_t)cb * 64;
            #pragma unroll
            for (int kc = 0; kc < 2; kc++) {
                uint32_t v[4];
                ldmx4(v, va + kc * 32);
                mma16816(o[dt], pH[kc], v[0], v[1]);
                mma16816(o[dt], pH[kc], v[2], v[3]);
            }
        }
    }

    sum0 += __shfl_xor_sync(0xffffffffu, sum0, 1);
    sum0 += __shfl_xor_sync(0xffffffffu, sum0, 2);
    sum1 += __shfl_xor_sync(0xffffffffu, sum1, 1);
    sum1 += __shfl_xor_sync(0xffffffffu, sum1, 2);
    float rinv0 = __fdividef(1.0f, sum0);
    float rinv1 = __fdividef(1.0f, sum1);

    __syncthreads();
    #pragma unroll
    for (int dt = 0; dt < 4; dt++) {
        int d = dt * 8 + 2 * tig;
        Osm[d * 132 + r0 + g]           = o[dt][0] * rinv0;
        Osm[(d + 1) * 132 + r0 + g]     = o[dt][1] * rinv0;
        Osm[d * 132 + r0 + g + 8]       = o[dt][2] * rinv1;
        Osm[(d + 1) * 132 + r0 + g + 8] = o[dt][3] * rinv1;
    }
    __syncthreads();

    float* ob = dout + ((size_t)(n * C_ + h * D_)) * S_ + s0;
    #pragma unroll
    for (int j = 0; j < 4; j++) {
        int i = t + j * 256;
        int d = i >> 5, c4 = (i & 31) << 2;
        float4 ov = *(float4*)&Osm[d * 132 + c4];
        float4 fv = *(const float4*)(fb + (size_t)d * S_ + c4);
        ov.x += fv.x; ov.y += fv.y; ov.z += fv.z; ov.w += fv.w;
        *(float4*)(ob + (size_t)d * S_ + c4) = ov;
    }
}

// ---------------------------------------------------------------------------
extern "C" void kernel_launch(void* const* d_in, const int* in_sizes, int n_in,
                              void* d_out, int out_size)
{
    const float* feature = (const float*)d_in[0];
    const float* token   = (const float*)d_in[1];
    const float* Wv      = (const float*)d_in[2];
    const float* bv      = (const float*)d_in[3];
    const float* Wk      = (const float*)d_in[4];
    const float* bk      = (const float*)d_in[5];
    const float* Wq      = (const float*)d_in[6];
    const float* bq      = (const float*)d_in[7];
    float* out = (float*)d_out;

    cudaFuncSetAttribute(proj_mma_kernel,
                         cudaFuncAttributeMaxDynamicSharedMemorySize, PJ_TOT);
    cudaFuncSetAttribute(attn_mma_kernel,
                         cudaFuncAttributeMaxDynamicSharedMemorySize, SB_TOT);

    proj_mma_kernel<<<dim3(L_/128, C_/128, N_*2), 256, PJ_TOT>>>(token, Wv, bv, Wk, bk);
    attn_mma_kernel<<<dim3(S_/128, H_, N_), 256, SB_TOT>>>(feature, Wq, bq, out);
}

// round 14
// speedup vs baseline: 1.3245x; 1.2343x over previous
#include <cuda_runtime.h>
#include <cuda_bf16.h>
#include <cstdint>
#include <math.h>

#define N_  4
#define C_  512
#define CT_ 512
#define L_  256
#define S_  4096
#define H_  16
#define D_  32

// bf16 (hi-only) K/V in fragment-ready layouts (written by proj kernel)
// K: [n][h][l(256)][kp(16)]   kp = channel-pair within head
// V: [n][h][d(32)][lp(128)]   lp = l-pair
__device__ uint32_t g_KH[(size_t)N_ * H_ * L_ * 16];
__device__ uint32_t g_VH[(size_t)N_ * H_ * D_ * 128];

// ---------------- helpers ----------------
__device__ __forceinline__ float ex2f(float x) {
    float r; asm("ex2.approx.f32 %0, %1;" : "=f"(r) : "f"(x)); return r;
}
__device__ __forceinline__ uint32_t pack_bf2(float lo, float hi) {
    uint32_t r; asm("cvt.rn.bf16x2.f32 %0, %1, %2;" : "=r"(r) : "f"(hi), "f"(lo)); return r;
}
__device__ __forceinline__ float bf_lo(uint32_t r) { return __uint_as_float(r << 16); }
__device__ __forceinline__ float bf_hi(uint32_t r) { return __uint_as_float(r & 0xFFFF0000u); }
__device__ __forceinline__ void split2(float x0, float x1, uint32_t& hp, uint32_t& lp) {
    hp = pack_bf2(x0, x1);
    lp = pack_bf2(x0 - bf_lo(hp), x1 - bf_hi(hp));
}
__device__ __forceinline__ void mma16816(float* c, const uint32_t* a, uint32_t b0, uint32_t b1) {
    asm volatile("mma.sync.aligned.m16n8k16.row.col.f32.bf16.bf16.f32 "
                 "{%0,%1,%2,%3}, {%4,%5,%6,%7}, {%8,%9}, {%0,%1,%2,%3};"
                 : "+f"(c[0]), "+f"(c[1]), "+f"(c[2]), "+f"(c[3])
                 : "r"(a[0]), "r"(a[1]), "r"(a[2]), "r"(a[3]), "r"(b0), "r"(b1));
}
__device__ __forceinline__ void ldmx4(uint32_t* r, uint32_t addr) {
    asm volatile("ldmatrix.sync.aligned.m8n8.x4.shared.b16 {%0,%1,%2,%3}, [%4];"
                 : "=r"(r[0]), "=r"(r[1]), "=r"(r[2]), "=r"(r[3]) : "r"(addr));
}
__device__ __forceinline__ uint32_t smem_u32(const void* p) {
    uint32_t a;
    asm("{ .reg .u64 t; cvta.to.shared.u64 t, %1; cvt.u32.u64 %0, t; }" : "=r"(a) : "l"(p));
    return a;
}

// ---------------------------------------------------------------------------
// Kernel A: K/V projection as bf16-split mma GEMM (3-pass internal precision),
// epilogue emits bf16 hi-only in fragment-ready global layouts (coalesced).
// ---------------------------------------------------------------------------
#define PJ_ASH  0
#define PJ_ASL  8704
#define PJ_BSH  17408
#define PJ_BSL  27648
#define PJ_TOT  67584          // Csm[128][132] f32 reuses from offset 0

extern "C" __global__ void __launch_bounds__(256, 1)
proj_mma_kernel(const float* __restrict__ token,
                const float* __restrict__ Wv, const float* __restrict__ bv,
                const float* __restrict__ Wk, const float* __restrict__ bk)
{
    extern __shared__ char smem[];
    uint32_t* ASH = (uint32_t*)(smem + PJ_ASH);
    uint32_t* ASL = (uint32_t*)(smem + PJ_ASL);
    uint32_t* BSH = (uint32_t*)(smem + PJ_BSH);
    uint32_t* BSL = (uint32_t*)(smem + PJ_BSL);
    float*    Csm = (float*)smem;
    const uint32_t sb = smem_u32(smem);

    const int t    = threadIdx.x;
    const int lane = t & 31;
    const int wid  = t >> 5;
    const int g    = lane >> 2;
    const int tig  = lane & 3;
    const int l0 = blockIdx.x * 128;
    const int o0 = blockIdx.y * 128;
    const int n = blockIdx.z >> 1, which = blockIdx.z & 1;   // 0 -> V, 1 -> K
    const float* __restrict__ W    = which ? Wk : Wv;
    const float* __restrict__ bias = which ? bk : bv;
    const float* tb = token + (size_t)n * CT_ * L_;

    const uint32_t kbase = sb + (lane < 16 ? PJ_BSH : PJ_BSL)
                         + ((uint32_t)(lane & 7) * 20 + ((uint32_t)((lane >> 3) & 1)) * 4) * 4;
    const int r0 = wid * 16;

    float c[16][4] = {};

    for (int kc = 0; kc < CT_; kc += 32) {
        __syncthreads();
        // stage A: W[o0+row][kc + 2cp..2cp+1] -> ASH/ASL[cp][row]
        #pragma unroll
        for (int i = t; i < 2048; i += 256) {
            int row = i >> 4, cp = i & 15;
            float2 w = *(const float2*)(W + (size_t)(o0 + row) * CT_ + kc + 2 * cp);
            uint32_t hp, lp; split2(w.x, w.y, hp, lp);
            ASH[cp * 136 + row] = hp;
            ASL[cp * 136 + row] = lp;
        }
        // stage B: token[kc+2cp..][l0+l] -> BSH/BSL[l][cp]
        #pragma unroll
        for (int i = t; i < 2048; i += 256) {
            int cp = i >> 7, l = i & 127;
            float t0 = tb[(size_t)(kc + 2 * cp) * L_ + l0 + l];
            float t1 = tb[(size_t)(kc + 2 * cp + 1) * L_ + l0 + l];
            uint32_t hp, lp; split2(t0, t1, hp, lp);
            BSH[l * 20 + cp] = hp;
            BSL[l * 20 + cp] = lp;
        }
        __syncthreads();

        uint32_t aH[2][4], aL[2][4];
        #pragma unroll
        for (int ks = 0; ks < 2; ks++) {
            int p0 = ks * 8 + tig;
            aH[ks][0] = ASH[p0 * 136 + r0 + g];
            aH[ks][1] = ASH[p0 * 136 + r0 + g + 8];
            aH[ks][2] = ASH[(p0 + 4) * 136 + r0 + g];
            aH[ks][3] = ASH[(p0 + 4) * 136 + r0 + g + 8];
            aL[ks][0] = ASL[p0 * 136 + r0 + g];
            aL[ks][1] = ASL[p0 * 136 + r0 + g + 8];
            aL[ks][2] = ASL[(p0 + 4) * 136 + r0 + g];
            aL[ks][3] = ASL[(p0 + 4) * 136 + r0 + g + 8];
        }
        #pragma unroll
        for (int nt = 0; nt < 16; nt++) {
            const uint32_t ka = kbase + (uint32_t)nt * 640;
            #pragma unroll
            for (int ks = 0; ks < 2; ks++) {
                uint32_t b[4];
                ldmx4(b, ka + ks * 32);
                mma16816(c[nt], aH[ks], b[0], b[1]);   // hi*hi
                mma16816(c[nt], aH[ks], b[2], b[3]);   // hi*lo
                mma16816(c[nt], aL[ks], b[0], b[1]);   // lo*hi
            }
        }
    }
    __syncthreads();

    // dump C to smem [row=channel 128][col=l 132-stride]
    #pragma unroll
    for (int nt = 0; nt < 16; nt++) {
        int col = nt * 8 + 2 * tig;
        Csm[(r0 + g) * 132 + col]           = c[nt][0];
        Csm[(r0 + g) * 132 + col + 1]       = c[nt][1];
        Csm[(r0 + g + 8) * 132 + col]       = c[nt][2];
        Csm[(r0 + g + 8) * 132 + col + 1]   = c[nt][3];
    }
    __syncthreads();

    if (which) {
        // K epilogue, coalesced: lanes sweep kp fastest -> contiguous stores
        #pragma unroll
        for (int i = t; i < 8192; i += 256) {
            int kp = i & 15;
            int l  = (i >> 4) & 127;
            int hh = i >> 11;                     // head within block 0..3
            int op = hh * 16 + kp;                // channel-pair row in Csm
            int ch = o0 + 2 * op;
            float v0 = Csm[(2 * op) * 132 + l]     + bias[ch];
            float v1 = Csm[(2 * op + 1) * 132 + l] + bias[ch + 1];
            int h = ch >> 5;
            size_t dst = ((size_t)(n * H_ + h) * L_ + l0 + l) * 16 + kp;
            g_KH[dst] = pack_bf2(v0, v1);
        }
    } else {
        // V epilogue (coalesced: consecutive lc -> contiguous)
        #pragma unroll
        for (int i = t; i < 8192; i += 256) {
            int r = i >> 6, lc = i & 63;
            int ch = o0 + r;
            float bb = bias[ch];
            float v0 = Csm[r * 132 + 2 * lc]     + bb;
            float v1 = Csm[r * 132 + 2 * lc + 1] + bb;
            int h = ch >> 5, d = ch & 31;
            size_t dst = ((size_t)(n * H_ + h) * D_ + d) * 128 + (l0 >> 1) + lc;
            g_VH[dst] = pack_bf2(v0, v1);
        }
    }
}

// ---------------------------------------------------------------------------
// Kernel B: pure-bf16 mma.sync attention.
// One ldmatrix.x4 per (cb,nt) yields all 4 B-frags (both k-steps) of that
// n-tile: lane-group g addresses col-offset 4g. Same for V per (cb,dt).
// smem: F 32x132 f32 | WQ | QH 16x136 u32 | KH 256x20 u32 | VH 32x132 u32
// ---------------------------------------------------------------------------
#define SB_F    0          // 32x132 f32 (F; Osm after mainloop)
#define SB_WQ   16896      // 1024 f32
#define SB_QHI  20992      // 16x136 u32
#define SB_KHI  29696      // 256x20 u32  (20480 B)
#define SB_VHI  50176      // 32x132 u32  (16896 B)
#define SB_TOT  67072

extern "C" __global__ void __launch_bounds__(256, 2)
attn_mma_kernel(const float* __restrict__ feature,
                const float* __restrict__ Wq, const float* __restrict__ bq,
                float* __restrict__ dout)
{
    extern __shared__ char smem[];
    float*    smf = (float*)smem;
    uint32_t* QH  = (uint32_t*)(smem + SB_QHI);
    uint32_t* KH  = (uint32_t*)(smem + SB_KHI);
    uint32_t* VH  = (uint32_t*)(smem + SB_VHI);
    float*    Osm = (float*)smem;

    const int t    = threadIdx.x;
    const int lane = t & 31;
    const int wid  = t >> 5;
    const int g    = lane >> 2;
    const int tig  = lane & 3;
    const int s0 = blockIdx.x * 128;
    const int h  = blockIdx.y;
    const int n  = blockIdx.z;
    const uint32_t sb = smem_u32(smem);

    // ---------------- stage tiles (pure copies) ----------------
    const float* fb = feature + ((size_t)(n * C_ + h * D_)) * S_ + s0;
    #pragma unroll
    for (int i = t; i < 1024; i += 256) {
        int row = i >> 5, c4 = (i & 31) << 2;
        *(float4*)&smf[row * 132 + c4] = *(const float4*)(fb + (size_t)row * S_ + c4);
    }
    #pragma unroll
    for (int i = t; i < 1024; i += 256)
        smf[SB_WQ/4 + i] = Wq[h * 1024 + i];

    const uint32_t* gkh = g_KH + (size_t)(n * H_ + h) * L_ * 16;
    #pragma unroll
    for (int i = t; i < 1024; i += 256) {                 // K: 256 rows x 16 u32
        int l = i >> 2, c = (i & 3) << 2;
        *(uint4*)&KH[l * 20 + c] = *(const uint4*)(gkh + l * 16 + c);
    }
    const uint32_t* gvh = g_VH + (size_t)(n * H_ + h) * D_ * 128;
    #pragma unroll
    for (int i = t; i < 1024; i += 256) {                 // V: 32 rows x 128 u32
        int d = i >> 5, c = (i & 31) << 2;
        *(uint4*)&VH[d * 132 + c] = *(const uint4*)(gvh + d * 128 + c);
    }
    __syncthreads();

    // ---------------- Q projection -> bf16 (hi only) in smem ----------------
    {
        const int row = t & 127;
        const int d0  = (t >> 7) << 4;
        float acc[16] = {};
        #pragma unroll 8
        for (int i = 0; i < 32; i++) {
            float f = smf[i * 132 + row];
            #pragma unroll
            for (int dd = 0; dd < 16; dd++)
                acc[dd] += smf[SB_WQ/4 + (d0 + dd) * 32 + i] * f;
        }
        const float scale = 0.2550354839f;                // (1/sqrt(32))*log2(e)
        #pragma unroll
        for (int j = 0; j < 8; j++) {
            int d = d0 + 2 * j;
            float q0 = (acc[2*j]   + bq[h*D_ + d])   * scale;
            float q1 = (acc[2*j+1] + bq[h*D_ + d+1]) * scale;
            QH[(d >> 1) * 136 + row] = pack_bf2(q0, q1);
        }
    }
    __syncthreads();

    const int r0 = wid * 16;
    uint32_t aH[2][4];
    #pragma unroll
    for (int ks = 0; ks < 2; ks++) {
        int p0 = ks * 8 + tig;
        aH[ks][0] = QH[p0 * 136 + r0 + g];
        aH[ks][1] = QH[p0 * 136 + r0 + g + 8];
        aH[ks][2] = QH[(p0 + 4) * 136 + r0 + g];
        aH[ks][3] = QH[(p0 + 4) * 136 + r0 + g + 8];
    }
    __syncthreads();

    // per-lane ldmatrix bases: lane-group (lane>>3) selects col offset 4g
    const uint32_t kbase = sb + SB_KHI
                         + ((uint32_t)(lane & 7) * 20 + (uint32_t)(lane >> 3) * 4) * 4;
    const uint32_t vbase = sb + SB_VHI
                         + ((uint32_t)(lane & 7) * 132 + (uint32_t)(lane >> 3) * 4) * 4;

    float o[4][4] = {};
    float sum0 = 0.f, sum1 = 0.f;

    #pragma unroll 1
    for (int cb = 0; cb < 8; cb++) {
        // ---- GEMM1: one ldmx4 per nt gives both k-steps ----
        float c[4][4] = {};
        #pragma unroll
        for (int nt = 0; nt < 4; nt++) {
            uint32_t b[4];
            ldmx4(b, kbase + (uint32_t)(cb * 32 + nt * 8) * 80);
            mma16816(c[nt], aH[0], b[0], b[1]);   // ks0
            mma16816(c[nt], aH[1], b[2], b[3]);   // ks1
        }
        // ---- exp + partial row sums ----
        float e[4][4];
        #pragma unroll
        for (int nt = 0; nt < 4; nt++) {
            e[nt][0] = ex2f(c[nt][0]);
            e[nt][1] = ex2f(c[nt][1]);
            e[nt][2] = ex2f(c[nt][2]);
            e[nt][3] = ex2f(c[nt][3]);
            sum0 += e[nt][0] + e[nt][1];
            sum1 += e[nt][2] + e[nt][3];
        }
        // ---- P -> bf16, register-to-register ----
        uint32_t pH[2][4];
        #pragma unroll
        for (int kc = 0; kc < 2; kc++) {
            int t0 = 2 * kc, t1 = 2 * kc + 1;
            pH[kc][0] = pack_bf2(e[t0][0], e[t0][1]);
            pH[kc][1] = pack_bf2(e[t0][2], e[t0][3]);
            pH[kc][2] = pack_bf2(e[t1][0], e[t1][1]);
            pH[kc][3] = pack_bf2(e[t1][2], e[t1][3]);
        }
        // ---- GEMM2: one ldmx4 per dt gives both k-chunks ----
        #pragma unroll
        for (int dt = 0; dt < 4; dt++) {
            uint32_t v[4];
            ldmx4(v, vbase + (uint32_t)dt * 4224 + (uint32_t)cb * 64);
            mma16816(o[dt], pH[0], v[0], v[1]);   // kc0
            mma16816(o[dt], pH[1], v[2], v[3]);   // kc1
        }
    }

    sum0 += __shfl_xor_sync(0xffffffffu, sum0, 1);
    sum0 += __shfl_xor_sync(0xffffffffu, sum0, 2);
    sum1 += __shfl_xor_sync(0xffffffffu, sum1, 1);
    sum1 += __shfl_xor_sync(0xffffffffu, sum1, 2);
    float rinv0 = __fdividef(1.0f, sum0);
    float rinv1 = __fdividef(1.0f, sum1);

    __syncthreads();
    #pragma unroll
    for (int dt = 0; dt < 4; dt++) {
        int d = dt * 8 + 2 * tig;
        Osm[d * 132 + r0 + g]           = o[dt][0] * rinv0;
        Osm[(d + 1) * 132 + r0 + g]     = o[dt][1] * rinv0;
        Osm[d * 132 + r0 + g + 8]       = o[dt][2] * rinv1;
        Osm[(d + 1) * 132 + r0 + g + 8] = o[dt][3] * rinv1;
    }
    __syncthreads();

    float* ob = dout + ((size_t)(n * C_ + h * D_)) * S_ + s0;
    #pragma unroll
    for (int j = 0; j < 4; j++) {
        int i = t + j * 256;
        int d = i >> 5, c4 = (i & 31) << 2;
        float4 ov = *(float4*)&Osm[d * 132 + c4];
        float4 fv = *(const float4*)(fb + (size_t)d * S_ + c4);
        ov.x += fv.x; ov.y += fv.y; ov.z += fv.z; ov.w += fv.w;
        *(float4*)(ob + (size_t)d * S_ + c4) = ov;
    }
}

// ---------------------------------------------------------------------------
extern "C" void kernel_launch(void* const* d_in, const int* in_sizes, int n_in,
                              void* d_out, int out_size)
{
    const float* feature = (const float*)d_in[0];
    const float* token   = (const float*)d_in[1];
    const float* Wv      = (const float*)d_in[2];
    const float* bv      = (const float*)d_in[3];
    const float* Wk      = (const float*)d_in[4];
    const float* bk      = (const float*)d_in[5];
    const float* Wq      = (const float*)d_in[6];
    const float* bq      = (const float*)d_in[7];
    float* out = (float*)d_out;

    cudaFuncSetAttribute(proj_mma_kernel,
                         cudaFuncAttributeMaxDynamicSharedMemorySize, PJ_TOT);
    cudaFuncSetAttribute(attn_mma_kernel,
                         cudaFuncAttributeMaxDynamicSharedMemorySize, SB_TOT);

    proj_mma_kernel<<<dim3(L_/128, C_/128, N_*2), 256, PJ_TOT>>>(token, Wv, bv, Wk, bk);
    attn_mma_kernel<<<dim3(S_/128, H_, N_), 256, SB_TOT>>>(feature, Wq, bq, out);
}

// round 16
// speedup vs baseline: 1.5835x; 1.1955x over previous
#include <cuda_runtime.h>
#include <cuda_bf16.h>
#include <cstdint>
#include <math.h>

#define N_  4
#define C_  512
#define CT_ 512
#define L_  256
#define S_  4096
#define H_  16
#define D_  32

// bf16 (hi-only) K/V in fragment-ready layouts (written by proj kernel)
// K: [n][h][l(256)][kp(16)]   kp = channel-pair within head
// V: [n][h][d(32)][lp(128)]   lp = l-pair
__device__ uint32_t g_KH[(size_t)N_ * H_ * L_ * 16];
__device__ uint32_t g_VH[(size_t)N_ * H_ * D_ * 128];

// ---------------- helpers ----------------
__device__ __forceinline__ float ex2f(float x) {
    float r; asm("ex2.approx.f32 %0, %1;" : "=f"(r) : "f"(x)); return r;
}
__device__ __forceinline__ uint32_t pack_bf2(float lo, float hi) {
    uint32_t r; asm("cvt.rn.bf16x2.f32 %0, %1, %2;" : "=r"(r) : "f"(hi), "f"(lo)); return r;
}
__device__ __forceinline__ float bf_lo(uint32_t r) { return __uint_as_float(r << 16); }
__device__ __forceinline__ float bf_hi(uint32_t r) { return __uint_as_float(r & 0xFFFF0000u); }
__device__ __forceinline__ void split2(float x0, float x1, uint32_t& hp, uint32_t& lp) {
    hp = pack_bf2(x0, x1);
    lp = pack_bf2(x0 - bf_lo(hp), x1 - bf_hi(hp));
}
__device__ __forceinline__ void mma16816(float* c, const uint32_t* a, uint32_t b0, uint32_t b1) {
    asm volatile("mma.sync.aligned.m16n8k16.row.col.f32.bf16.bf16.f32 "
                 "{%0,%1,%2,%3}, {%4,%5,%6,%7}, {%8,%9}, {%0,%1,%2,%3};"
                 : "+f"(c[0]), "+f"(c[1]), "+f"(c[2]), "+f"(c[3])
                 : "r"(a[0]), "r"(a[1]), "r"(a[2]), "r"(a[3]), "r"(b0), "r"(b1));
}
__device__ __forceinline__ void ldmx4(uint32_t* r, uint32_t addr) {
    asm volatile("ldmatrix.sync.aligned.m8n8.x4.shared.b16 {%0,%1,%2,%3}, [%4];"
                 : "=r"(r[0]), "=r"(r[1]), "=r"(r[2]), "=r"(r[3]) : "r"(addr));
}
__device__ __forceinline__ uint32_t smem_u32(const void* p) {
    uint32_t a;
    asm("{ .reg .u64 t; cvta.to.shared.u64 t, %1; cvt.u32.u64 %0, t; }" : "=r"(a) : "l"(p));
    return a;
}

// ---------------------------------------------------------------------------
// Kernel A: K/V projection as bf16-split mma GEMM — unchanged from round 14.
// ---------------------------------------------------------------------------
#define PJ_ASH  0
#define PJ_ASL  8704
#define PJ_BSH  17408
#define PJ_BSL  27648
#define PJ_TOT  67584          // Csm[128][132] f32 reuses from offset 0

extern "C" __global__ void __launch_bounds__(256, 1)
proj_mma_kernel(const float* __restrict__ token,
                const float* __restrict__ Wv, const float* __restrict__ bv,
                const float* __restrict__ Wk, const float* __restrict__ bk)
{
    extern __shared__ char smem[];
    uint32_t* ASH = (uint32_t*)(smem + PJ_ASH);
    uint32_t* ASL = (uint32_t*)(smem + PJ_ASL);
    uint32_t* BSH = (uint32_t*)(smem + PJ_BSH);
    uint32_t* BSL = (uint32_t*)(smem + PJ_BSL);
    float*    Csm = (float*)smem;
    const uint32_t sb = smem_u32(smem);

    const int t    = threadIdx.x;
    const int lane = t & 31;
    const int wid  = t >> 5;
    const int g    = lane >> 2;
    const int tig  = lane & 3;
    const int l0 = blockIdx.x * 128;
    const int o0 = blockIdx.y * 128;
    const int n = blockIdx.z >> 1, which = blockIdx.z & 1;   // 0 -> V, 1 -> K
    const float* __restrict__ W    = which ? Wk : Wv;
    const float* __restrict__ bias = which ? bk : bv;
    const float* tb = token + (size_t)n * CT_ * L_;

    const uint32_t kbase = sb + (lane < 16 ? PJ_BSH : PJ_BSL)
                         + ((uint32_t)(lane & 7) * 20 + ((uint32_t)((lane >> 3) & 1)) * 4) * 4;
    const int r0 = wid * 16;

    float c[16][4] = {};

    for (int kc = 0; kc < CT_; kc += 32) {
        __syncthreads();
        #pragma unroll
        for (int i = t; i < 2048; i += 256) {
            int row = i >> 4, cp = i & 15;
            float2 w = *(const float2*)(W + (size_t)(o0 + row) * CT_ + kc + 2 * cp);
            uint32_t hp, lp; split2(w.x, w.y, hp, lp);
            ASH[cp * 136 + row] = hp;
            ASL[cp * 136 + row] = lp;
        }
        #pragma unroll
        for (int i = t; i < 2048; i += 256) {
            int cp = i >> 7, l = i & 127;
            float t0 = tb[(size_t)(kc + 2 * cp) * L_ + l0 + l];
            float t1 = tb[(size_t)(kc + 2 * cp + 1) * L_ + l0 + l];
            uint32_t hp, lp; split2(t0, t1, hp, lp);
            BSH[l * 20 + cp] = hp;
            BSL[l * 20 + cp] = lp;
        }
        __syncthreads();

        uint32_t aH[2][4], aL[2][4];
        #pragma unroll
        for (int ks = 0; ks < 2; ks++) {
            int p0 = ks * 8 + tig;
            aH[ks][0] = ASH[p0 * 136 + r0 + g];
            aH[ks][1] = ASH[p0 * 136 + r0 + g + 8];
            aH[ks][2] = ASH[(p0 + 4) * 136 + r0 + g];
            aH[ks][3] = ASH[(p0 + 4) * 136 + r0 + g + 8];
            aL[ks][0] = ASL[p0 * 136 + r0 + g];
            aL[ks][1] = ASL[p0 * 136 + r0 + g + 8];
            aL[ks][2] = ASL[(p0 + 4) * 136 + r0 + g];
            aL[ks][3] = ASL[(p0 + 4) * 136 + r0 + g + 8];
        }
        #pragma unroll
        for (int nt = 0; nt < 16; nt++) {
            const uint32_t ka = kbase + (uint32_t)nt * 640;
            #pragma unroll
            for (int ks = 0; ks < 2; ks++) {
                uint32_t b[4];
                ldmx4(b, ka + ks * 32);
                mma16816(c[nt], aH[ks], b[0], b[1]);
                mma16816(c[nt], aH[ks], b[2], b[3]);
                mma16816(c[nt], aL[ks], b[0], b[1]);
            }
        }
    }
    __syncthreads();

    #pragma unroll
    for (int nt = 0; nt < 16; nt++) {
        int col = nt * 8 + 2 * tig;
        Csm[(r0 + g) * 132 + col]           = c[nt][0];
        Csm[(r0 + g) * 132 + col + 1]       = c[nt][1];
        Csm[(r0 + g + 8) * 132 + col]       = c[nt][2];
        Csm[(r0 + g + 8) * 132 + col + 1]   = c[nt][3];
    }
    __syncthreads();

    if (which) {
        #pragma unroll
        for (int i = t; i < 8192; i += 256) {
            int kp = i & 15;
            int l  = (i >> 4) & 127;
            int hh = i >> 11;
            int op = hh * 16 + kp;
            int ch = o0 + 2 * op;
            float v0 = Csm[(2 * op) * 132 + l]     + bias[ch];
            float v1 = Csm[(2 * op + 1) * 132 + l] + bias[ch + 1];
            int h = ch >> 5;
            size_t dst = ((size_t)(n * H_ + h) * L_ + l0 + l) * 16 + kp;
            g_KH[dst] = pack_bf2(v0, v1);
        }
    } else {
        #pragma unroll
        for (int i = t; i < 8192; i += 256) {
            int r = i >> 6, lc = i & 63;
            int ch = o0 + r;
            float bb = bias[ch];
            float v0 = Csm[r * 132 + 2 * lc]     + bb;
            float v1 = Csm[r * 132 + 2 * lc + 1] + bb;
            int h = ch >> 5, d = ch & 31;
            size_t dst = ((size_t)(n * H_ + h) * D_ + d) * 128 + (l0 >> 1) + lc;
            g_VH[dst] = pack_bf2(v0, v1);
        }
    }
}

// ---------------------------------------------------------------------------
// Kernel B: pure-bf16 mma.sync attention with TENSORIZED Q projection.
// smem: FB[16][136] u32 | WQB[32][20] u32 | KH[256][20] u32 | VH[32][132] u32
// Osm (32x132 f32) overlays FB/WQB/head-of-KH after the mainloop.
// ---------------------------------------------------------------------------
#define AB_FB   0          // 8704 B
#define AB_WQB  8704       // 2560 B
#define AB_KH   11264      // 20480 B
#define AB_VH   31744      // 16896 B
#define AB_TOT  48640

extern "C" __global__ void __launch_bounds__(256, 2)
attn_mma_kernel(const float* __restrict__ feature,
                const float* __restrict__ Wq, const float* __restrict__ bq,
                float* __restrict__ dout)
{
    extern __shared__ char smem[];
    uint32_t* FB  = (uint32_t*)(smem + AB_FB);
    uint32_t* WQB = (uint32_t*)(smem + AB_WQB);
    uint32_t* KH  = (uint32_t*)(smem + AB_KH);
    uint32_t* VH  = (uint32_t*)(smem + AB_VH);
    float*    Osm = (float*)smem;

    const int t    = threadIdx.x;
    const int lane = t & 31;
    const int wid  = t >> 5;
    const int g    = lane >> 2;
    const int tig  = lane & 3;
    const int s0 = blockIdx.x * 128;
    const int h  = blockIdx.y;
    const int n  = blockIdx.z;
    const uint32_t sb = smem_u32(smem);
    const float scale = 0.2550354839f;                    // (1/sqrt(32))*log2(e)

    // ---------------- stage tiles ----------------
    const float* fb = feature + ((size_t)(n * C_ + h * D_)) * S_ + s0;
    #pragma unroll
    for (int i = t; i < 2048; i += 256) {                 // F -> bf16 [ip][row]
        int row = i & 127, ip = i >> 7;
        float f0 = fb[(size_t)(2 * ip) * S_ + row];
        float f1 = fb[(size_t)(2 * ip + 1) * S_ + row];
        FB[ip * 136 + row] = pack_bf2(f0, f1);
    }
    #pragma unroll
    for (int i = t; i < 512; i += 256) {                  // Wq*scale -> bf16 [d][ip]
        int d = i >> 4, ip = i & 15;
        float w0 = Wq[h * 1024 + d * 32 + 2 * ip]     * scale;
        float w1 = Wq[h * 1024 + d * 32 + 2 * ip + 1] * scale;
        WQB[d * 20 + ip] = pack_bf2(w0, w1);
    }
    const uint32_t* gkh = g_KH + (size_t)(n * H_ + h) * L_ * 16;
    #pragma unroll
    for (int i = t; i < 1024; i += 256) {                 // K: 256 rows x 16 u32
        int l = i >> 2, c = (i & 3) << 2;
        *(uint4*)&KH[l * 20 + c] = *(const uint4*)(gkh + l * 16 + c);
    }
    const uint32_t* gvh = g_VH + (size_t)(n * H_ + h) * D_ * 128;
    #pragma unroll
    for (int i = t; i < 1024; i += 256) {                 // V: 32 rows x 128 u32
        int d = i >> 5, c = (i & 31) << 2;
        *(uint4*)&VH[d * 132 + c] = *(const uint4*)(gvh + d * 128 + c);
    }
    __syncthreads();

    const int r0 = wid * 16;

    // ---------------- Q projection via MMA (once) ----------------
    uint32_t aH[2][4];
    {
        uint32_t fa[2][4];
        #pragma unroll
        for (int ks = 0; ks < 2; ks++) {
            int p0 = ks * 8 + tig;
            fa[ks][0] = FB[p0 * 136 + r0 + g];
            fa[ks][1] = FB[p0 * 136 + r0 + g + 8];
            fa[ks][2] = FB[(p0 + 4) * 136 + r0 + g];
            fa[ks][3] = FB[(p0 + 4) * 136 + r0 + g + 8];
        }
        float qc[4][4] = {};
        #pragma unroll
        for (int dt = 0; dt < 4; dt++) {
            #pragma unroll
            for (int ks = 0; ks < 2; ks++) {
                uint32_t b0 = WQB[(dt * 8 + g) * 20 + ks * 8 + tig];
                uint32_t b1 = WQB[(dt * 8 + g) * 20 + ks * 8 + tig + 4];
                mma16816(qc[dt], fa[ks], b0, b1);
            }
        }
        // bq*scale add + C-frag -> A-frag pack (register-only)
        #pragma unroll
        for (int ks = 0; ks < 2; ks++) {
            float2 b0 = *(const float2*)&bq[h * 32 + (2 * ks) * 8 + 2 * tig];
            float2 b1 = *(const float2*)&bq[h * 32 + (2 * ks + 1) * 8 + 2 * tig];
            aH[ks][0] = pack_bf2(qc[2*ks][0]   + b0.x * scale, qc[2*ks][1]   + b0.y * scale);
            aH[ks][1] = pack_bf2(qc[2*ks][2]   + b0.x * scale, qc[2*ks][3]   + b0.y * scale);
            aH[ks][2] = pack_bf2(qc[2*ks+1][0] + b1.x * scale, qc[2*ks+1][1] + b1.y * scale);
            aH[ks][3] = pack_bf2(qc[2*ks+1][2] + b1.x * scale, qc[2*ks+1][3] + b1.y * scale);
        }
    }

    // per-lane ldmatrix bases: lane-group (lane>>3) selects col offset 4g
    const uint32_t kbase = sb + AB_KH
                         + ((uint32_t)(lane & 7) * 20 + (uint32_t)(lane >> 3) * 4) * 4;
    const uint32_t vbase = sb + AB_VH
                         + ((uint32_t)(lane & 7) * 132 + (uint32_t)(lane >> 3) * 4) * 4;

    float o[4][4] = {};
    float sum0 = 0.f, sum1 = 0.f;

    #pragma unroll 1
    for (int cb = 0; cb < 8; cb++) {
        // ---- GEMM1 ----
        float c[4][4] = {};
        #pragma unroll
        for (int nt = 0; nt < 4; nt++) {
            uint32_t b[4];
            ldmx4(b, kbase + (uint32_t)(cb * 32 + nt * 8) * 80);
            mma16816(c[nt], aH[0], b[0], b[1]);
            mma16816(c[nt], aH[1], b[2], b[3]);
        }
        // ---- exp + partial row sums ----
        float e[4][4];
        #pragma unroll
        for (int nt = 0; nt < 4; nt++) {
            e[nt][0] = ex2f(c[nt][0]);
            e[nt][1] = ex2f(c[nt][1]);
            e[nt][2] = ex2f(c[nt][2]);
            e[nt][3] = ex2f(c[nt][3]);
            sum0 += e[nt][0] + e[nt][1];
            sum1 += e[nt][2] + e[nt][3];
        }
        // ---- P -> bf16 ----
        uint32_t pH[2][4];
        #pragma unroll
        for (int kc = 0; kc < 2; kc++) {
            int t0 = 2 * kc, t1 = 2 * kc + 1;
            pH[kc][0] = pack_bf2(e[t0][0], e[t0][1]);
            pH[kc][1] = pack_bf2(e[t0][2], e[t0][3]);
            pH[kc][2] = pack_bf2(e[t1][0], e[t1][1]);
            pH[kc][3] = pack_bf2(e[t1][2], e[t1][3]);
        }
        // ---- GEMM2 ----
        #pragma unroll
        for (int dt = 0; dt < 4; dt++) {
            uint32_t v[4];
            ldmx4(v, vbase + (uint32_t)dt * 4224 + (uint32_t)cb * 64);
            mma16816(o[dt], pH[0], v[0], v[1]);
            mma16816(o[dt], pH[1], v[2], v[3]);
        }
    }

    sum0 += __shfl_xor_sync(0xffffffffu, sum0, 1);
    sum0 += __shfl_xor_sync(0xffffffffu, sum0, 2);
    sum1 += __shfl_xor_sync(0xffffffffu, sum1, 1);
    sum1 += __shfl_xor_sync(0xffffffffu, sum1, 2);
    float rinv0 = __fdividef(1.0f, sum0);
    float rinv1 = __fdividef(1.0f, sum1);

    __syncthreads();
    #pragma unroll
    for (int dt = 0; dt < 4; dt++) {
        int d = dt * 8 + 2 * tig;
        Osm[d * 132 + r0 + g]           = o[dt][0] * rinv0;
        Osm[(d + 1) * 132 + r0 + g]     = o[dt][1] * rinv0;
        Osm[d * 132 + r0 + g + 8]       = o[dt][2] * rinv1;
        Osm[(d + 1) * 132 + r0 + g + 8] = o[dt][3] * rinv1;
    }
    __syncthreads();

    float* ob = dout + ((size_t)(n * C_ + h * D_)) * S_ + s0;
    #pragma unroll
    for (int j = 0; j < 4; j++) {
        int i = t + j * 256;
        int d = i >> 5, c4 = (i & 31) << 2;
        float4 ov = *(float4*)&Osm[d * 132 + c4];
        float4 fv = *(const float4*)(fb + (size_t)d * S_ + c4);
        ov.x += fv.x; ov.y += fv.y; ov.z += fv.z; ov.w += fv.w;
        *(float4*)(ob + (size_t)d * S_ + c4) = ov;
    }
}

// ---------------------------------------------------------------------------
extern "C" void kernel_launch(void* const* d_in, const int* in_sizes, int n_in,
                              void* d_out, int out_size)
{
    const float* feature = (const float*)d_in[0];
    const float* token   = (const float*)d_in[1];
    const float* Wv      = (const float*)d_in[2];
    const float* bv      = (const float*)d_in[3];
    const float* Wk      = (const float*)d_in[4];
    const float* bk      = (const float*)d_in[5];
    const float* Wq      = (const float*)d_in[6];
    const float* bq      = (const float*)d_in[7];
    float* out = (float*)d_out;

    cudaFuncSetAttribute(proj_mma_kernel,
                         cudaFuncAttributeMaxDynamicSharedMemorySize, PJ_TOT);
    cudaFuncSetAttribute(attn_mma_kernel,
                         cudaFuncAttributeMaxDynamicSharedMemorySize, AB_TOT);

    proj_mma_kernel<<<dim3(L_/128, C_/128, N_*2), 256, PJ_TOT>>>(token, Wv, bv, Wk, bk);
    attn_mma_kernel<<<dim3(S_/128, H_, N_), 256, AB_TOT>>>(feature, Wq, bq, out);
}